// round 16
// baseline (speedup 1.0000x reference)
#include <cuda_runtime.h>
#include <math.h>

#define Bx 8
#define Nx 1024
#define Cx 64
#define Ox 64
#define Mx 4                 // K+1
#define BN (Bx*Nx)           // 8192
#define BNO (BN*Ox)          // 524288

// ---------------- scratch (device globals; no allocations allowed) ----------
__device__ float g_sRi[BN], g_sIi[BN], g_sRj[BN], g_sIj[BN];
__device__ float g_cmax[BN], g_rsum[BN];
__device__ float g_rowR[Bx*Mx*Nx], g_rowI[Bx*Mx*Nx];
__device__ float g_pR[(size_t)Mx*BNO], g_pI[(size_t)Mx*BNO];   // combined partials [m][idx]

// ---------------- kernel A: attention projections ---------------------------
__global__ void __launch_bounds__(256) kA(const float* __restrict__ Xr,
                                          const float* __restrict__ Xi,
                                          const float* __restrict__ awr,
                                          const float* __restrict__ awi)
{
    int gw   = (blockIdx.x * blockDim.x + threadIdx.x) >> 5;
    int lane = threadIdx.x & 31;
    if (gw >= BN) return;
    const float* xr = Xr + (size_t)gw * Cx;
    const float* xi = Xi + (size_t)gw * Cx;
    float a1=0.f,a2=0.f,a3=0.f,a4=0.f,a5=0.f,a6=0.f,a7=0.f,a8=0.f;
#pragma unroll
    for (int k = 0; k < 2; k++) {
        int c = lane + (k << 5);
        float xrv = xr[c], xiv = xi[c];
        float wri = awr[c],      wii = awi[c];
        float wrj = awr[Cx + c], wij = awi[Cx + c];
        a1 = fmaf(xrv, wri, a1);  a2 = fmaf(xiv, wii, a2);
        a3 = fmaf(xrv, wii, a3);  a4 = fmaf(xiv, wri, a4);
        a5 = fmaf(xrv, wrj, a5);  a6 = fmaf(xiv, wij, a6);
        a7 = fmaf(xrv, wij, a7);  a8 = fmaf(xiv, wrj, a8);
    }
#pragma unroll
    for (int off = 16; off; off >>= 1) {
        a1 += __shfl_xor_sync(0xffffffffu, a1, off);
        a2 += __shfl_xor_sync(0xffffffffu, a2, off);
        a3 += __shfl_xor_sync(0xffffffffu, a3, off);
        a4 += __shfl_xor_sync(0xffffffffu, a4, off);
        a5 += __shfl_xor_sync(0xffffffffu, a5, off);
        a6 += __shfl_xor_sync(0xffffffffu, a6, off);
        a7 += __shfl_xor_sync(0xffffffffu, a7, off);
        a8 += __shfl_xor_sync(0xffffffffu, a8, off);
    }
    if (lane == 0) {
        g_sRi[gw] = a1 - a2;
        g_sIi[gw] = a3 + a4;
        g_sRj[gw] = a5 - a6;
        g_sIj[gw] = a7 + a8;
    }
}

// ---------------- kernel B: per-(b,j) softmax stats over i ------------------
__global__ void __launch_bounds__(256) kB(const float* __restrict__ br,
                                          const float* __restrict__ bi,
                                          const float* __restrict__ par,
                                          const float* __restrict__ pai)
{
    __shared__ float sri_s[Nx], sii_s[Nx];
    __shared__ float red[8];
    int b  = blockIdx.x >> 8;
    int j0 = (blockIdx.x & 255) << 2;
    float biasr = br[0], biasi = bi[0];
    float apr = par[0], api = pai[0];
    for (int t = threadIdx.x; t < Nx; t += 256) {
        sri_s[t] = g_sRi[b*Nx + t] + biasr;
        sii_s[t] = g_sIi[b*Nx + t] + biasi;
    }
    __syncthreads();
    int lane = threadIdx.x & 31, wid = threadIdx.x >> 5;
    for (int jj = 0; jj < 4; jj++) {
        int j = j0 + jj;
        float sjr = g_sRj[b*Nx + j];
        float sji = g_sIj[b*Nx + j];
        float mags[4];
        float lmax = -1e30f;
#pragma unroll
        for (int k = 0; k < 4; k++) {
            int i = threadIdx.x + (k << 8);
            float scr = sri_s[i] + sjr;
            float sci = sii_s[i] + sji;
            float pr = scr >= 0.f ? scr : apr * scr;
            float pi = sci >= 0.f ? sci : api * sci;
            float s2 = fmaf(pr, pr, pi * pi);
            float rm = rsqrtf(fmaxf(s2, 1e-36f));
            float mg = s2 * rm;
            mags[k] = mg;
            lmax = fmaxf(lmax, mg);
        }
#pragma unroll
        for (int off = 16; off; off >>= 1)
            lmax = fmaxf(lmax, __shfl_xor_sync(0xffffffffu, lmax, off));
        if (lane == 0) red[wid] = lmax;
        __syncthreads();
        float M = red[0];
#pragma unroll
        for (int t = 1; t < 8; t++) M = fmaxf(M, red[t]);
        __syncthreads();
        float ls = 0.f;
#pragma unroll
        for (int k = 0; k < 4; k++) ls += __expf(mags[k] - M);
#pragma unroll
        for (int off = 16; off; off >>= 1)
            ls += __shfl_xor_sync(0xffffffffu, ls, off);
        if (lane == 0) red[wid] = ls;
        __syncthreads();
        if (threadIdx.x == 0) {
            float S = red[0]+red[1]+red[2]+red[3]+red[4]+red[5]+red[6]+red[7];
            g_cmax[b*Nx + j] = M;
            g_rsum[b*Nx + j] = 1.0f / S;
        }
        __syncthreads();
    }
}

// ---------------- kernel C v2 (measured best 50us): plain, 80 regs ----------
__global__ void __launch_bounds__(256) kC(const float* __restrict__ Lr,
                                          const float* __restrict__ Li,
                                          const float* __restrict__ br,
                                          const float* __restrict__ bi,
                                          const float* __restrict__ par,
                                          const float* __restrict__ pai)
{
    __shared__ float sjr_s[Nx], sji_s[Nx], cm_s[Nx], rs_s[Nx];
    int b  = blockIdx.x >> 7;
    int i0 = (blockIdx.x & 127) << 3;
    for (int t = threadIdx.x; t < Nx; t += 256) {
        sjr_s[t] = g_sRj[b*Nx + t];
        sji_s[t] = g_sIj[b*Nx + t];
        cm_s[t]  = g_cmax[b*Nx + t];
        rs_s[t]  = g_rsum[b*Nx + t];
    }
    __syncthreads();
    int wid = threadIdx.x >> 5, lane = threadIdx.x & 31;
    int i = i0 + wid;
    float sri = g_sRi[b*Nx + i] + br[0];
    float sii = g_sIi[b*Nx + i] + bi[0];
    float apr = par[0], api = pai[0];
    const size_t MS = (size_t)Nx * Nx;
    const float* pR = Lr + (size_t)b * Mx * MS + (size_t)i * Nx;
    const float* pI = Li + (size_t)b * Mx * MS + (size_t)i * Nx;

    float aR[4] = {0.f,0.f,0.f,0.f};
    float aI[4] = {0.f,0.f,0.f,0.f};

#pragma unroll 1
    for (int jb = 0; jb < Nx; jb += 128) {
        int j0 = jb + (lane << 2);
        float4 R0 = __ldcs((const float4*)(pR          + j0));
        float4 R1 = __ldcs((const float4*)(pR +   MS   + j0));
        float4 R2 = __ldcs((const float4*)(pR + 2*MS   + j0));
        float4 R3 = __ldcs((const float4*)(pR + 3*MS   + j0));
        float4 I0 = __ldcs((const float4*)(pI          + j0));
        float4 I1 = __ldcs((const float4*)(pI +   MS   + j0));
        float4 I2 = __ldcs((const float4*)(pI + 2*MS   + j0));
        float4 I3 = __ldcs((const float4*)(pI + 3*MS   + j0));
        float4 vjr = *(const float4*)&sjr_s[j0];
        float4 vji = *(const float4*)&sji_s[j0];
        float4 vcm = *(const float4*)&cm_s[j0];
        float4 vrs = *(const float4*)&rs_s[j0];

        float ar[4], ai[4];
        const float* jr = (const float*)&vjr;
        const float* ji = (const float*)&vji;
        const float* cm = (const float*)&vcm;
        const float* rs = (const float*)&vrs;
#pragma unroll
        for (int q = 0; q < 4; q++) {
            float scr = sri + jr[q];
            float sci = sii + ji[q];
            float pr = scr >= 0.f ? scr : apr * scr;
            float pi = sci >= 0.f ? sci : api * sci;
            float s2 = fmaf(pr, pr, pi * pi);
            float rm = rsqrtf(fmaxf(s2, 1e-36f));
            float mg = s2 * rm;
            float sc = __fdividef(__expf(mg - cm[q]) * rs[q], mg + 1e-12f);
            ar[q] = sc * pr;
            ai[q] = sc * pi;
        }
        const float* r0 = (const float*)&R0; const float* i0p = (const float*)&I0;
        const float* r1 = (const float*)&R1; const float* i1p = (const float*)&I1;
        const float* r2 = (const float*)&R2; const float* i2p = (const float*)&I2;
        const float* r3 = (const float*)&R3; const float* i3p = (const float*)&I3;
#pragma unroll
        for (int q = 0; q < 4; q++) {
            aR[0] = fmaf(r0[q], ar[q], fmaf(i0p[q], -ai[q], aR[0]));
            aI[0] = fmaf(r0[q], ai[q], fmaf(i0p[q],  ar[q], aI[0]));
            aR[1] = fmaf(r1[q], ar[q], fmaf(i1p[q], -ai[q], aR[1]));
            aI[1] = fmaf(r1[q], ai[q], fmaf(i1p[q],  ar[q], aI[1]));
            aR[2] = fmaf(r2[q], ar[q], fmaf(i2p[q], -ai[q], aR[2]));
            aI[2] = fmaf(r2[q], ai[q], fmaf(i2p[q],  ar[q], aI[2]));
            aR[3] = fmaf(r3[q], ar[q], fmaf(i3p[q], -ai[q], aR[3]));
            aI[3] = fmaf(r3[q], ai[q], fmaf(i3p[q],  ar[q], aI[3]));
        }
    }
#pragma unroll
    for (int off = 16; off; off >>= 1) {
#pragma unroll
        for (int m = 0; m < 4; m++) {
            aR[m] += __shfl_xor_sync(0xffffffffu, aR[m], off);
            aI[m] += __shfl_xor_sync(0xffffffffu, aI[m], off);
        }
    }
    if (lane == 0) {
        size_t o = (size_t)b * Mx * Nx + i;
#pragma unroll
        for (int m = 0; m < 4; m++) {
            g_rowR[o + m*Nx] = aR[m];
            g_rowI[o + m*Nx] = aI[m];
        }
    }
}

// ---------------- kernel D v9: m-split GEMM, 128-row tiles, single wave -----
// grid 256 = 4 m x 64 row-tiles. Block: 256 threads, 128 rows x 64 outs,
// 8x4 thread tiles. smem 102.4KB -> exactly 2 blocks/SM -> 296 capacity,
// 256 blocks = ONE wave, 16 warps/SM.
__global__ void __launch_bounds__(256, 2) kD(const float* __restrict__ Xr,
                                             const float* __restrict__ Xi,
                                             const float* __restrict__ wr,
                                             const float* __restrict__ wi)
{
    extern __shared__ __align__(16) float sm[];
    float* Xr_s = sm;                        // [64][132]  (c-major, 128 rows+pad)
    float* Xi_s = sm + 64*132;               // [64][132]
    float* wr_s = sm + 2*64*132;             // [64][68]
    float* wi_s = sm + 2*64*132 + 64*68;     // [64][68]

    int tid  = threadIdx.x;
    int m    = blockIdx.x & 3;
    int tile = blockIdx.x >> 2;
    int r0 = tile << 7;                      // 128 rows per block
    int b  = r0 >> 10;
    int jbase = r0 & 1023;

    // stage X tile transposed: 2048 (row, cgroup) float4 tasks per tensor
#pragma unroll
    for (int it = 0; it < 8; it++) {
        int idx = tid + (it << 8);           // 0..2047
        int r  = idx >> 4;                   // 0..127
        int cg = (idx & 15) << 2;            // 0..60
        float4 v = __ldg((const float4*)(Xr + (size_t)(r0 + r)*64 + cg));
        Xr_s[(cg+0)*132 + r] = v.x;
        Xr_s[(cg+1)*132 + r] = v.y;
        Xr_s[(cg+2)*132 + r] = v.z;
        Xr_s[(cg+3)*132 + r] = v.w;
        float4 u = __ldg((const float4*)(Xi + (size_t)(r0 + r)*64 + cg));
        Xi_s[(cg+0)*132 + r] = u.x;
        Xi_s[(cg+1)*132 + r] = u.y;
        Xi_s[(cg+2)*132 + r] = u.z;
        Xi_s[(cg+3)*132 + r] = u.w;
    }
    // stage this m's weights [c][o]
    {
        const float4* wrg = (const float4*)(wr + (size_t)m * 4096);
        const float4* wig = (const float4*)(wi + (size_t)m * 4096);
#pragma unroll
        for (int k = 0; k < 4; k++) {
            int idx = tid + (k << 8);        // 0..1023
            int c = idx >> 4, og = (idx & 15) << 2;
            *(float4*)&wr_s[c*68 + og] = __ldg(wrg + idx);
            *(float4*)&wi_s[c*68 + og] = __ldg(wig + idx);
        }
    }
    __syncthreads();

    int tx = tid & 15, ty = tid >> 4;        // tx: out-group (16), ty: row-group (16)
    int oo = tx << 2;                        // outputs oo..oo+3
    int rr = ty << 3;                        // rows rr..rr+7

    float pR[8][4], pI[8][4];
#pragma unroll
    for (int r = 0; r < 8; r++)
#pragma unroll
        for (int o = 0; o < 4; o++) { pR[r][o] = 0.f; pI[r][o] = 0.f; }

#pragma unroll 4
    for (int c = 0; c < 64; c++) {
        float4 xa0 = *(const float4*)&Xr_s[c*132 + rr];
        float4 xa1 = *(const float4*)&Xr_s[c*132 + rr + 4];
        float4 ya0 = *(const float4*)&Xi_s[c*132 + rr];
        float4 ya1 = *(const float4*)&Xi_s[c*132 + rr + 4];
        float4 wv  = *(const float4*)&wr_s[c*68 + oo];
        float4 vv  = *(const float4*)&wi_s[c*68 + oo];
        float xa[8] = {xa0.x, xa0.y, xa0.z, xa0.w, xa1.x, xa1.y, xa1.z, xa1.w};
        float ya[8] = {ya0.x, ya0.y, ya0.z, ya0.w, ya1.x, ya1.y, ya1.z, ya1.w};
        float wa[4] = {wv.x,  wv.y,  wv.z,  wv.w};
        float va[4] = {vv.x,  vv.y,  vv.z,  vv.w};
#pragma unroll
        for (int r = 0; r < 8; r++)
#pragma unroll
            for (int o = 0; o < 4; o++) {
                pR[r][o] = fmaf(xa[r], wa[o], pR[r][o]);
                pI[r][o] = fmaf(ya[r], va[o], pI[r][o]);
            }
    }

    // epilogue: fold rowR/rowI, store coalesced combined partials
    float* gR = g_pR + (size_t)m * BNO;
    float* gI = g_pI + (size_t)m * BNO;
#pragma unroll
    for (int r = 0; r < 8; r++) {
        size_t o = (size_t)(b*Mx + m)*Nx + jbase + rr + r;
        float cRr = __ldg(&g_rowR[o]);
        float cIr = __ldg(&g_rowI[o]);
        size_t idx = (size_t)(r0 + rr + r) * 64 + oo;
        float4 vr, vi;
        vr.x = fmaf(cRr, pR[r][0], -cIr * pI[r][0]);
        vr.y = fmaf(cRr, pR[r][1], -cIr * pI[r][1]);
        vr.z = fmaf(cRr, pR[r][2], -cIr * pI[r][2]);
        vr.w = fmaf(cRr, pR[r][3], -cIr * pI[r][3]);
        vi.x = fmaf(cIr, pR[r][0],  cRr * pI[r][0]);
        vi.y = fmaf(cIr, pR[r][1],  cRr * pI[r][1]);
        vi.z = fmaf(cIr, pR[r][2],  cRr * pI[r][2]);
        vi.w = fmaf(cIr, pR[r][3],  cRr * pI[r][3]);
        *(float4*)(gR + idx) = vr;
        *(float4*)(gI + idx) = vi;
    }
}

// ---------------- kernel E v3: sum 4 m-partials, 8 floats/thread ------------
__global__ void __launch_bounds__(256) kE(float* __restrict__ out)
{
    size_t t   = (size_t)blockIdx.x * 256 + threadIdx.x;
    size_t idx = t << 3;                 // 8 consecutive floats

    float4 r00 = *(const float4*)&g_pR[idx];
    float4 r01 = *(const float4*)&g_pR[idx + 4];
    float4 r10 = *(const float4*)&g_pR[(size_t)BNO + idx];
    float4 r11 = *(const float4*)&g_pR[(size_t)BNO + idx + 4];
    float4 r20 = *(const float4*)&g_pR[(size_t)2*BNO + idx];
    float4 r21 = *(const float4*)&g_pR[(size_t)2*BNO + idx + 4];
    float4 r30 = *(const float4*)&g_pR[(size_t)3*BNO + idx];
    float4 r31 = *(const float4*)&g_pR[(size_t)3*BNO + idx + 4];
    float4 i00 = *(const float4*)&g_pI[idx];
    float4 i01 = *(const float4*)&g_pI[idx + 4];
    float4 i10 = *(const float4*)&g_pI[(size_t)BNO + idx];
    float4 i11 = *(const float4*)&g_pI[(size_t)BNO + idx + 4];
    float4 i20 = *(const float4*)&g_pI[(size_t)2*BNO + idx];
    float4 i21 = *(const float4*)&g_pI[(size_t)2*BNO + idx + 4];
    float4 i30 = *(const float4*)&g_pI[(size_t)3*BNO + idx];
    float4 i31 = *(const float4*)&g_pI[(size_t)3*BNO + idx + 4];

    float4 vr0, vr1, vi0, vi1;
    vr0.x = (r00.x + r10.x) + (r20.x + r30.x);
    vr0.y = (r00.y + r10.y) + (r20.y + r30.y);
    vr0.z = (r00.z + r10.z) + (r20.z + r30.z);
    vr0.w = (r00.w + r10.w) + (r20.w + r30.w);
    vr1.x = (r01.x + r11.x) + (r21.x + r31.x);
    vr1.y = (r01.y + r11.y) + (r21.y + r31.y);
    vr1.z = (r01.z + r11.z) + (r21.z + r31.z);
    vr1.w = (r01.w + r11.w) + (r21.w + r31.w);
    vi0.x = (i00.x + i10.x) + (i20.x + i30.x);
    vi0.y = (i00.y + i10.y) + (i20.y + i30.y);
    vi0.z = (i00.z + i10.z) + (i20.z + i30.z);
    vi0.w = (i00.w + i10.w) + (i20.w + i30.w);
    vi1.x = (i01.x + i11.x) + (i21.x + i31.x);
    vi1.y = (i01.y + i11.y) + (i21.y + i31.y);
    vi1.z = (i01.z + i11.z) + (i21.z + i31.z);
    vi1.w = (i01.w + i11.w) + (i21.w + i31.w);

    *(float4*)(out + idx)                   = vr0;
    *(float4*)(out + idx + 4)               = vr1;
    *(float4*)(out + (size_t)BNO + idx)     = vi0;
    *(float4*)(out + (size_t)BNO + idx + 4) = vi1;
}

// ---------------- launch (serial, single stream) ----------------------------
extern "C" void kernel_launch(void* const* d_in, const int* in_sizes, int n_in,
                              void* d_out, int out_size)
{
    const float* Xr  = (const float*)d_in[0];
    const float* Xi  = (const float*)d_in[1];
    const float* Lr  = (const float*)d_in[2];
    const float* Li  = (const float*)d_in[3];
    const float* wr  = (const float*)d_in[4];
    const float* wi  = (const float*)d_in[5];
    const float* awr = (const float*)d_in[6];
    const float* awi = (const float*)d_in[7];
    const float* abr = (const float*)d_in[8];
    const float* abi = (const float*)d_in[9];
    const float* par = (const float*)d_in[10];
    const float* pai = (const float*)d_in[11];
    float* out = (float*)d_out;

    const int KD_SMEM = (2*64*132 + 2*64*68) * 4;   // 102400 bytes
    static int attr_done = 0;
    if (!attr_done) {
        cudaFuncSetAttribute(kD, cudaFuncAttributeMaxDynamicSharedMemorySize, KD_SMEM);
        attr_done = 1;
    }

    kA<<<BN/8, 256>>>(Xr, Xi, awr, awi);
    kB<<<Bx*256, 256>>>(abr, abi, par, pai);
    kC<<<Bx*128, 256>>>(Lr, Li, abr, abi, par, pai);
    kD<<<(BN/128)*4, 256, KD_SMEM>>>(Xr, Xi, wr, wi);
    kE<<<BNO/2048, 256>>>(out);
}